// round 7
// baseline (speedup 1.0000x reference)
#include <cuda_runtime.h>
#include <cuda_fp16.h>
#include <cstdint>
#include <cstddef>

// Problem constants
#define B_   16
#define T_   8
#define KB_  64
#define CO_  128
#define CI_  128
#define H_   64
#define W_   64
#define WELEMS (CO_*CI_*25)          // 409600

// ---------------------------------------------------------------------------
// Scratch (__device__ globals; allocation-free rule)
// ---------------------------------------------------------------------------
__device__ __align__(16) unsigned g_xh[(size_t)B_*64*H_*W_];       // half2 x planes [b][ci/2][h][w]
__device__ __align__(16) __half  g_lph[(size_t)B_*8*2*CO_*25*8];   // [b][cc][kk][co][tap][ci8]

// ---------------------------------------------------------------------------
// Kernel P: fused prep (wsum blocks + xcvt blocks, concurrent).
// ---------------------------------------------------------------------------
#define NWB 512
#define NXB 512

__global__ __launch_bounds__(256) void k_prep(const float* __restrict__ x,
                                              const float* __restrict__ tf,
                                              const float* __restrict__ Wb) {
    const int blk = blockIdx.x;
    const int tid = threadIdx.x;

    if (blk < NWB) {
        // ---------------- wsum part ----------------
        __shared__ float ss[B_*KB_];
        __shared__ __align__(16) float wbuf[2][800];

        for (int i = tid; i < B_*KB_; i += 256) {
            int b = i >> 6, k = i & 63;
            float a = 0.f;
            #pragma unroll
            for (int t = 0; t < T_; t++) a += tf[(b*T_ + t)*KB_ + k];
            ss[i] = a * (1.0f / T_);
        }
        __syncthreads();

        const int co = blk >> 2;
        const int q  = blk & 3;               // ci quarter (32 ci)
        const bool act = tid < 200;
        const float* src = Wb + co*3200 + q*800 + 4*tid;

        float4 acc[B_];
        #pragma unroll
        for (int b = 0; b < B_; b++) acc[b] = make_float4(0.f, 0.f, 0.f, 0.f);

        if (act) {
            #pragma unroll 4
            for (int k = 0; k < KB_; k++) {
                float4 wv = *(const float4*)(src + (size_t)k*WELEMS);
                #pragma unroll
                for (int b = 0; b < B_; b++) {
                    float sv = ss[b*KB_ + k];
                    acc[b].x += sv * wv.x;
                    acc[b].y += sv * wv.y;
                    acc[b].z += sv * wv.z;
                    acc[b].w += sv * wv.w;
                }
            }
        }

        // transpose 2 examples per pass through smem; coalesced 16B stores
        const int bsel = tid / 100;           // 0/1 (tid<200)
        const int t2   = tid % 100;
        const int tap  = t2 % 25;
        const int c8   = t2 / 25;             // ci8-block within quarter (0..3)
        #pragma unroll 1
        for (int bp = 0; bp < 8; bp++) {
            if (act) {
                *(float4*)(wbuf[0] + 4*tid) = acc[2*bp];
                *(float4*)(wbuf[1] + 4*tid) = acc[2*bp + 1];
            }
            __syncthreads();
            if (tid < 200) {
                __half h[8];
                #pragma unroll
                for (int i2 = 0; i2 < 8; i2++)
                    h[i2] = __float2half_rn(wbuf[bsel][(c8*8 + i2)*25 + tap]);
                int b  = 2*bp + bsel;
                int cc = q*2 + (c8 >> 1);
                int kk = c8 & 1;
                size_t o = (((((size_t)b*8 + cc)*2 + kk)*CO_ + co)*25 + tap)*8;
                *(uint4*)(g_lph + o) = *(const uint4*)h;
            }
            __syncthreads();
        }
    } else {
        // ---------------- xcvt part ----------------
        const size_t total4 = (size_t)B_*64*H_*W_ / 4;     // uint4 count
        for (size_t e = (size_t)(blk - NWB)*256 + tid; e < total4;
             e += (size_t)NXB*256) {
            size_t i = e * 4;
            int hw   = (int)(i & 4095);
            int rest = (int)(i >> 12);
            int pl   = rest & 63;
            int b    = rest >> 6;
            const float* xb = x + ((size_t)(b*CI_ + 2*pl))*4096 + hw;
            float4 lo = *(const float4*)xb;
            float4 hi = *(const float4*)(xb + 4096);
            uint4 o;
            __half2 p0 = __floats2half2_rn(lo.x, hi.x);
            __half2 p1 = __floats2half2_rn(lo.y, hi.y);
            __half2 p2 = __floats2half2_rn(lo.z, hi.z);
            __half2 p3 = __floats2half2_rn(lo.w, hi.w);
            o.x = *(unsigned*)&p0; o.y = *(unsigned*)&p1;
            o.z = *(unsigned*)&p2; o.w = *(unsigned*)&p3;
            *(uint4*)(g_xh + i) = o;
        }
    }
}

// ---------------------------------------------------------------------------
// Kernel C: fp16 m16n8k16 conv.
// 256-thread CTA (8 warps), tile 64co x (4 rows x 64 px), warp 64co x 32px.
// Single smem buffer, 8 chunks of 16 ci; 2 CTAs/SM cover stage latency.
// ---------------------------------------------------------------------------
#define WS_TAPB   2048                     // bytes per tap slab (64co x 2 x 16B)
#define WS_BYTES  (25*WS_TAPB)             // 51200
#define XS_PLANE  584                      // words per ci-pair plane (8*72 + 8)
#define XS_WORDS  (8*XS_PLANE)             // 4672
#define SMEM_BYTES (WS_BYTES + XS_WORDS*4) // 69888

__device__ __forceinline__ void cp16(void* dst, const void* src) {
    unsigned d = (unsigned)__cvta_generic_to_shared(dst);
    asm volatile("cp.async.cg.shared.global [%0], [%1], 16;" :: "r"(d), "l"(src));
}
__device__ __forceinline__ void ldsm4(unsigned* r, unsigned addr) {
    asm volatile("ldmatrix.sync.aligned.m8n8.x4.shared.b16 {%0,%1,%2,%3}, [%4];"
                 : "=r"(r[0]), "=r"(r[1]), "=r"(r[2]), "=r"(r[3]) : "r"(addr));
}
__device__ __forceinline__ void mma16(float* d, const unsigned* a, const unsigned* bb) {
    asm volatile("mma.sync.aligned.m16n8k16.row.col.f32.f16.f16.f32 "
                 "{%0,%1,%2,%3}, {%4,%5,%6,%7}, {%8,%9}, {%0,%1,%2,%3};"
                 : "+f"(d[0]), "+f"(d[1]), "+f"(d[2]), "+f"(d[3])
                 : "r"(a[0]), "r"(a[1]), "r"(a[2]), "r"(a[3]), "r"(bb[0]), "r"(bb[1]));
}

__global__ __launch_bounds__(256, 2) void k_conv(float* __restrict__ y) {
    extern __shared__ __align__(128) unsigned char smem[];
    unsigned char* WS = smem;                       // swizzled weight slab
    unsigned*      XS = (unsigned*)(smem + WS_BYTES);

    const int tid = threadIdx.x;
    const int ln  = tid & 31;
    const int w   = tid >> 5;
    const int g   = ln >> 2;
    const int tig = ln & 3;
    const int wr  = w >> 1;              // output row within tile (0..3)
    const int cw  = (w & 1) * 32;        // column half

    const int h0  = blockIdx.x * 4;
    const int co0 = blockIdx.y * 64;
    const int b   = blockIdx.z;

    const unsigned ws_s = (unsigned)__cvta_generic_to_shared(WS);
    const unsigned swzA = ((unsigned)(((ln & 15) << 1) | ((ln >> 4) ^ ((ln >> 2) & 1)))) << 4;

    // zero XS once: halo cols + OOB rows stay zero for all chunks
    for (int i = tid; i < XS_WORDS; i += 256) XS[i] = 0;

    float acc[4][4][4];
    #pragma unroll
    for (int mf = 0; mf < 4; mf++)
        #pragma unroll
        for (int f = 0; f < 4; f++)
            #pragma unroll
            for (int r = 0; r < 4; r++) acc[mf][f][r] = 0.f;

    __syncthreads();

    #pragma unroll 1
    for (int cc = 0; cc < 8; cc++) {
        // ---- stage weights: 3200 x 16B ----
        #pragma unroll 1
        for (int e = tid; e < 3200; e += 256) {
            int kk  = e / 1600;
            int r   = e - kk*1600;
            int co  = r / 25;
            int tap = r - co*25;
            const __half* src = g_lph +
                (((((size_t)b*8 + cc)*2 + kk)*CO_ + co0 + co)*25 + tap)*8;
            int swz = (co*2 + (kk ^ ((co >> 2) & 1)))*16;
            cp16(WS + tap*WS_TAPB + swz, src);
        }
        // ---- stage x planes: 8 planes x 8 halo rows x 16 quads ----
        #pragma unroll 1
        for (int e = tid; e < 1024; e += 256) {
            int pl  = e >> 7;
            int rem = e & 127;
            int r   = rem >> 4;
            int qd  = rem & 15;
            int gh  = h0 - 2 + r;
            if ((unsigned)gh < H_) {
                const unsigned* src = g_xh + (((size_t)(b*64 + cc*8 + pl)*64 + gh) << 6) + qd*4;
                cp16(XS + pl*XS_PLANE + r*72 + 4 + qd*4, src);
            }
        }
        asm volatile("cp.async.commit_group;");
        asm volatile("cp.async.wait_group 0;");
        __syncthreads();

        const int xbase = wr*72 + 2 + cw + g;
        #pragma unroll
        for (int dh = 0; dh < 5; dh++) {
            #pragma unroll
            for (int dw = 0; dw < 5; dw++) {
                const int tap = dh*5 + dw;
                unsigned a[4][4];
                #pragma unroll
                for (int mf = 0; mf < 4; mf++)
                    ldsm4(a[mf], ws_s + tap*WS_TAPB + swzA + mf*512);

                unsigned bb[4][2];
                const int xo = xbase + dh*72 + dw;
                #pragma unroll
                for (int f = 0; f < 4; f++) {
                    bb[f][0] = XS[tig*XS_PLANE       + xo + 8*f];
                    bb[f][1] = XS[(tig + 4)*XS_PLANE + xo + 8*f];
                }
                #pragma unroll
                for (int mf = 0; mf < 4; mf++)
                    #pragma unroll
                    for (int f = 0; f < 4; f++)
                        mma16(acc[mf][f], a[mf], bb[f]);
            }
        }
        __syncthreads();
    }

    // epilogue
    const int hw = h0 + wr;
    #pragma unroll
    for (int mf = 0; mf < 4; mf++) {
        #pragma unroll
        for (int f = 0; f < 4; f++) {
            int co = co0 + 16*mf + g;
            int px = cw + 8*f + 2*tig;
            float* yp = y + (((size_t)b*CO_ + co)*H_ + hw)*W_ + px;
            *(float2*)yp             = make_float2(acc[mf][f][0], acc[mf][f][1]);
            *(float2*)(yp + 8*H_*W_) = make_float2(acc[mf][f][2], acc[mf][f][3]);
        }
    }
}

// ---------------------------------------------------------------------------
// Launch
// ---------------------------------------------------------------------------
extern "C" void kernel_launch(void* const* d_in, const int* in_sizes, int n_in,
                              void* d_out, int out_size) {
    const float* x  = (const float*)d_in[0];
    const float* tf = (const float*)d_in[1];
    const float* Wb = (const float*)d_in[2];
    float* y        = (float*)d_out;

    cudaFuncSetAttribute(k_conv, cudaFuncAttributeMaxDynamicSharedMemorySize, SMEM_BYTES);

    k_prep<<<NWB + NXB, 256>>>(x, tf, Wb);
    dim3 grid(16, 2, B_);
    k_conv<<<grid, 256, SMEM_BYTES>>>(y);
    (void)in_sizes; (void)n_in; (void)out_size;
}